// round 2
// baseline (speedup 1.0000x reference)
#include <cuda_runtime.h>
#include <math.h>

#define VOCAB 4096
#define HID   512
#define BATCH 64
#define SEQ   512

// ---------------- scratch (static device globals; no allocation) ----------------
__device__ float    g_WihT[VOCAB * HID];          // 8 MB  : W_ih transposed [V,H]
__device__ float    g_xproj[SEQ * BATCH * HID];   // 64 MB : x_proj, layout [T,B,H]
__device__ float    g_outh [SEQ * BATCH * HID];   // 64 MB : hidden states, layout [T,B,H]
__device__ unsigned g_cnt[8];                     // per-batch-group barrier counters

// ---------------- transpose W_ih [H,V] -> g_WihT [V,H] ----------------
__global__ void k_transpose(const float* __restrict__ Wih) {
    __shared__ float tile[32][33];
    int v0 = blockIdx.x * 32;
    int h0 = blockIdx.y * 32;
    int tx = threadIdx.x, ty = threadIdx.y;   // 32 x 8
    #pragma unroll
    for (int i = ty; i < 32; i += 8)
        tile[i][tx] = Wih[(h0 + i) * VOCAB + v0 + tx];
    __syncthreads();
    #pragma unroll
    for (int i = ty; i < 32; i += 8)
        g_WihT[(v0 + i) * HID + h0 + tx] = tile[tx][i];
}

// ---------------- gather + bias: x_proj[t,b,:] = WihT[tok,:] + b_ih + b_hh ----------------
__global__ void k_gather(const int* __restrict__ inp,
                         const float* __restrict__ b_ih,
                         const float* __restrict__ b_hh) {
    int row = blockIdx.x;              // row = t*BATCH + b
    int t = row / BATCH;
    int b = row % BATCH;
    int tok = inp[b * SEQ + t];
    const float4* src = (const float4*)&g_WihT[tok * HID];
    const float4* bi4 = (const float4*)b_ih;
    const float4* bh4 = (const float4*)b_hh;
    float4* dst = (float4*)&g_xproj[row * HID];
    int i = threadIdx.x;               // 128 threads, HID/4 = 128
    float4 v = src[i];
    float4 bi = bi4[i], bh = bh4[i];
    v.x += bi.x + bh.x;  v.y += bi.y + bh.y;
    v.z += bi.z + bh.z;  v.w += bi.w + bh.w;
    dst[i] = v;
}

// ---------------- reset barrier counters (graph replays!) ----------------
__global__ void k_reset() {
    if (threadIdx.x < 8) g_cnt[threadIdx.x] = 0;
}

// ---------------- recurrence ----------------
// grid = 128 CTAs = 8 batch-groups (8 batches each) x 16 j-slices (32 j each)
// 128 threads/CTA. Dynamic smem: Ws[512][32] (64KB) + h_s[8][512] (16KB) = 80KB.
extern "C" __global__ void __launch_bounds__(128, 1)
k_rnn(const float* __restrict__ Whh, const float* __restrict__ h0g) {
    extern __shared__ float smem[];
    float* Ws = smem;                 // [k][j] : 512*32
    float* hs = smem + 512 * 32;      // [b][k] : 8*512

    int bx = blockIdx.x;
    int bg = bx & 7;                  // batch group 0..7
    int jg = bx >> 3;                 // j group 0..15
    int B0 = bg * 8;
    int J0 = jg * 32;
    int tid = threadIdx.x;

    // load W_hh slice into smem, transposed to [k][j]
    for (int j = 0; j < 32; j++) {
        const float* wr = Whh + (J0 + j) * HID;
        for (int k = tid; k < HID; k += 128)
            Ws[k * 32 + j] = wr[k];
    }

    int jl = tid & 31;
    int pr = tid >> 5;                // 0..3
    int b0 = pr * 2, b1 = pr * 2 + 1; // local batches
    const float* wp = Ws + jl;
    unsigned target = 0;
    __syncthreads();

    for (int t = 0; t < SEQ; t++) {
        // stage h_{t-1}[8,512] into smem (contiguous 16KB region)
        const float* hprev = (t == 0) ? (h0g + B0 * HID)
                                      : (g_outh + ((t - 1) * BATCH + B0) * HID);
        {
            float4* hd = (float4*)hs;
            const float4* hp = (const float4*)hprev;
            #pragma unroll
            for (int i = 0; i < 8; i++)
                hd[tid + i * 128] = hp[tid + i * 128];
        }
        __syncthreads();

        const float* xp = g_xproj + (t * BATCH + B0) * HID;
        float a0a = xp[b0 * HID + J0 + jl], a0b = 0.f;
        float a1a = xp[b1 * HID + J0 + jl], a1b = 0.f;
        const float* h0p = hs + b0 * HID;
        const float* h1p = hs + b1 * HID;

        #pragma unroll 2
        for (int k = 0; k < HID; k += 4) {
            float4 ha = *(const float4*)(h0p + k);
            float4 hb = *(const float4*)(h1p + k);
            float w0 = wp[(k + 0) * 32];
            float w1 = wp[(k + 1) * 32];
            float w2 = wp[(k + 2) * 32];
            float w3 = wp[(k + 3) * 32];
            a0a = fmaf(ha.x, w0, a0a);  a0b = fmaf(ha.y, w1, a0b);
            a0a = fmaf(ha.z, w2, a0a);  a0b = fmaf(ha.w, w3, a0b);
            a1a = fmaf(hb.x, w0, a1a);  a1b = fmaf(hb.y, w1, a1b);
            a1a = fmaf(hb.z, w2, a1a);  a1b = fmaf(hb.w, w3, a1b);
        }
        float r0 = tanhf(a0a + a0b);
        float r1 = tanhf(a1a + a1b);
        float* od = g_outh + (t * BATCH + B0) * HID;
        od[b0 * HID + J0 + jl] = r0;
        od[b1 * HID + J0 + jl] = r1;

        // group barrier: 16 CTAs of this batch group
        __threadfence();
        __syncthreads();
        if (tid == 0) atomicAdd(&g_cnt[bg], 1u);
        target += 16;
        if (tid == 0) {
            unsigned v;
            do {
                asm volatile("ld.acquire.gpu.u32 %0, [%1];" : "=r"(v) : "l"(&g_cnt[bg]));
            } while (v < target);
        }
        __syncthreads();
    }
}

// ---------------- FC GEMM: logits[b,t,v] = sum_k out_h[t,b,k]*W_fc[v,k] + b_fc[v] --------
// A = g_outh as [32768, 512] (row m = t*BATCH + b), B = W_fc [4096, 512]
// CTA tile 128m x 128v, k-tile 8, 256 threads, 8x8 register tile (4+4 split halves)
__global__ void __launch_bounds__(256, 1)
k_fc(const float* __restrict__ Wfc, const float* __restrict__ bfc,
     float* __restrict__ out) {
    __shared__ float As[8][128];
    __shared__ float Bs[8][128];

    int m0 = blockIdx.x * 128;
    int v0 = blockIdx.y * 128;
    int tid = threadIdx.x;
    int tx = tid & 15;      // 16 col groups
    int ty = tid >> 4;      // 16 row groups

    float acc[8][8];
    #pragma unroll
    for (int i = 0; i < 8; i++)
        #pragma unroll
        for (int j = 0; j < 8; j++) acc[i][j] = 0.f;

    int lrow = tid >> 1;        // 0..127
    int lcol = (tid & 1) * 4;   // 0 or 4
    const float* Aptr = g_outh + (size_t)(m0 + lrow) * HID + lcol;
    const float* Bptr = Wfc    + (size_t)(v0 + lrow) * HID + lcol;

    for (int kt = 0; kt < HID; kt += 8) {
        float4 a4 = *(const float4*)(Aptr + kt);
        float4 b4 = *(const float4*)(Bptr + kt);
        __syncthreads();
        As[lcol + 0][lrow] = a4.x;  As[lcol + 1][lrow] = a4.y;
        As[lcol + 2][lrow] = a4.z;  As[lcol + 3][lrow] = a4.w;
        Bs[lcol + 0][lrow] = b4.x;  Bs[lcol + 1][lrow] = b4.y;
        Bs[lcol + 2][lrow] = b4.z;  Bs[lcol + 3][lrow] = b4.w;
        __syncthreads();
        #pragma unroll
        for (int kk = 0; kk < 8; kk++) {
            float4 af0 = *(const float4*)&As[kk][ty * 4];
            float4 af1 = *(const float4*)&As[kk][64 + ty * 4];
            float4 bf0 = *(const float4*)&Bs[kk][tx * 4];
            float4 bf1 = *(const float4*)&Bs[kk][64 + tx * 4];
            float ar[8] = {af0.x, af0.y, af0.z, af0.w, af1.x, af1.y, af1.z, af1.w};
            float br[8] = {bf0.x, bf0.y, bf0.z, bf0.w, bf1.x, bf1.y, bf1.z, bf1.w};
            #pragma unroll
            for (int i = 0; i < 8; i++)
                #pragma unroll
                for (int j = 0; j < 8; j++)
                    acc[i][j] = fmaf(ar[i], br[j], acc[i][j]);
        }
    }

    // bias
    float4 bb0 = *(const float4*)&bfc[v0 + tx * 4];
    float4 bb1 = *(const float4*)&bfc[v0 + 64 + tx * 4];
    float bias[8] = {bb0.x, bb0.y, bb0.z, bb0.w, bb1.x, bb1.y, bb1.z, bb1.w};

    // epilogue: m = t*BATCH + b  ->  out index b*SEQ*VOCAB + t*VOCAB + v
    #pragma unroll
    for (int rh = 0; rh < 2; rh++) {
        #pragma unroll
        for (int ri = 0; ri < 4; ri++) {
            int m = m0 + rh * 64 + ty * 4 + ri;
            int b = m & (BATCH - 1);
            int t = m >> 6;
            size_t base = (size_t)b * SEQ * VOCAB + (size_t)t * VOCAB + v0;
            int r = rh * 4 + ri;
            float4 o0 = make_float4(acc[r][0] + bias[0], acc[r][1] + bias[1],
                                    acc[r][2] + bias[2], acc[r][3] + bias[3]);
            float4 o1 = make_float4(acc[r][4] + bias[4], acc[r][5] + bias[5],
                                    acc[r][6] + bias[6], acc[r][7] + bias[7]);
            *(float4*)&out[base + tx * 4]      = o0;
            *(float4*)&out[base + 64 + tx * 4] = o1;
        }
    }
}

// ---------------- copy h_last (t = SEQ-1, [B,H] contiguous) ----------------
__global__ void k_hid(float* __restrict__ out) {
    int i = blockIdx.x * 256 + threadIdx.x;
    out[i] = g_outh[(SEQ - 1) * BATCH * HID + i];
}

// ---------------- launcher ----------------
extern "C" void kernel_launch(void* const* d_in, const int* in_sizes, int n_in,
                              void* d_out, int out_size) {
    const int*   inp = (const int*)d_in[0];
    const float* hid = (const float*)d_in[1];
    const float* Wih = (const float*)d_in[2];
    const float* Whh = (const float*)d_in[3];
    const float* bih = (const float*)d_in[4];
    const float* bhh = (const float*)d_in[5];
    const float* Wfc = (const float*)d_in[6];
    const float* bfc = (const float*)d_in[7];
    float* out = (float*)d_out;

    cudaFuncSetAttribute(k_rnn, cudaFuncAttributeMaxDynamicSharedMemorySize, 81920);

    k_transpose<<<dim3(VOCAB / 32, HID / 32), dim3(32, 8)>>>(Wih);
    k_gather<<<SEQ * BATCH, 128>>>(inp, bih, bhh);
    k_reset<<<1, 32>>>();
    k_rnn<<<128, 128, 81920>>>(Whh, hid);
    k_fc<<<dim3(SEQ * BATCH / 128, VOCAB / 128), 256>>>(Wfc, bfc, out);

    long long logits_elems = (long long)BATCH * SEQ * VOCAB;
    if ((long long)out_size >= logits_elems + (long long)BATCH * HID) {
        k_hid<<<BATCH * HID / 256, 256>>>(out + logits_elems);
    }
}

// round 4
// speedup vs baseline: 1.3271x; 1.3271x over previous
#include <cuda_runtime.h>
#include <cuda_fp16.h>
#include <math.h>
#include <cstdint>

#define VOCAB 4096
#define HID   512
#define BATCH 64
#define SEQ   512
#define MROWS (SEQ * BATCH)

// ---------------- scratch (static device globals; no allocation) ----------------
__device__ float    g_WihT[VOCAB * HID];          // 8 MB  : W_ih transposed [V,H]
__device__ float    g_xproj[MROWS * HID];         // 64 MB : x_proj, layout [T,B,H]
__device__ float    g_outh [MROWS * HID];         // 64 MB : hidden states, layout [T,B,H]
__device__ __half   g_Ahi[MROWS * HID];           // 32 MB : fp16 hi of out_h
__device__ __half   g_Alo[MROWS * HID];           // 32 MB : fp16 lo of out_h
__device__ __half   g_Bhi[VOCAB * HID];           // 4 MB  : fp16 hi of W_fc
__device__ __half   g_Blo[VOCAB * HID];           // 4 MB  : fp16 lo of W_fc
__device__ unsigned g_cnt[8];                     // per-batch-group barrier counters

// ======================= helpers =======================
__device__ __forceinline__ uint32_t smem_u32(const void* p) {
    uint32_t a;
    asm("{ .reg .u64 t; cvta.to.shared.u64 t, %1; cvt.u32.u64 %0, t; }" : "=r"(a) : "l"(p));
    return a;
}
__device__ __forceinline__ void cp16(uint32_t dst, const void* src) {
    asm volatile("cp.async.cg.shared.global [%0], [%1], 16;" :: "r"(dst), "l"(src));
}
#define CP_COMMIT() asm volatile("cp.async.commit_group;" ::: "memory")
#define CP_WAIT(n)  asm volatile("cp.async.wait_group %0;" :: "n"(n) : "memory")

__device__ __forceinline__ uint32_t lds32(uint32_t a) {
    uint32_t v;
    asm("ld.shared.b32 %0, [%1];" : "=r"(v) : "r"(a));
    return v;
}
__device__ __forceinline__ void mma16816(float* c, uint32_t a0, uint32_t a1,
                                         uint32_t a2, uint32_t a3,
                                         uint32_t b0, uint32_t b1) {
    asm volatile("mma.sync.aligned.m16n8k16.row.col.f32.f16.f16.f32 "
                 "{%0,%1,%2,%3}, {%4,%5,%6,%7}, {%8,%9}, {%0,%1,%2,%3};"
                 : "+f"(c[0]), "+f"(c[1]), "+f"(c[2]), "+f"(c[3])
                 : "r"(a0), "r"(a1), "r"(a2), "r"(a3), "r"(b0), "r"(b1));
}

// ---------------- transpose W_ih [H,V] -> g_WihT [V,H] ----------------
__global__ void k_transpose(const float* __restrict__ Wih) {
    __shared__ float tile[32][33];
    int v0 = blockIdx.x * 32;
    int h0 = blockIdx.y * 32;
    int tx = threadIdx.x, ty = threadIdx.y;   // 32 x 8
    #pragma unroll
    for (int i = ty; i < 32; i += 8)
        tile[i][tx] = Wih[(h0 + i) * VOCAB + v0 + tx];
    __syncthreads();
    #pragma unroll
    for (int i = ty; i < 32; i += 8)
        g_WihT[(v0 + i) * HID + h0 + tx] = tile[tx][i];
}

// ---------------- gather + bias ----------------
__global__ void k_gather(const int* __restrict__ inp,
                         const float* __restrict__ b_ih,
                         const float* __restrict__ b_hh) {
    int row = blockIdx.x;              // row = t*BATCH + b
    int t = row / BATCH;
    int b = row % BATCH;
    int tok = inp[b * SEQ + t];
    const float4* src = (const float4*)&g_WihT[tok * HID];
    const float4* bi4 = (const float4*)b_ih;
    const float4* bh4 = (const float4*)b_hh;
    float4* dst = (float4*)&g_xproj[row * HID];
    int i = threadIdx.x;               // 128 threads
    float4 v = src[i];
    float4 bi = bi4[i], bh = bh4[i];
    v.x += bi.x + bh.x;  v.y += bi.y + bh.y;
    v.z += bi.z + bh.z;  v.w += bi.w + bh.w;
    dst[i] = v;
}

__global__ void k_reset() {
    if (threadIdx.x < 8) g_cnt[threadIdx.x] = 0;
}

// ---------------- recurrence (R2 design + fused fp16 hi/lo split of h) ----------------
extern "C" __global__ void __launch_bounds__(128, 1)
k_rnn(const float* __restrict__ Whh, const float* __restrict__ h0g) {
    extern __shared__ float smem[];
    float* Ws = smem;                 // [k][j] : 512*32
    float* hs = smem + 512 * 32;      // [b][k] : 8*512

    int bx = blockIdx.x;
    int bg = bx & 7;
    int jg = bx >> 3;
    int B0 = bg * 8;
    int J0 = jg * 32;
    int tid = threadIdx.x;

    for (int j = 0; j < 32; j++) {
        const float* wr = Whh + (J0 + j) * HID;
        for (int k = tid; k < HID; k += 128)
            Ws[k * 32 + j] = wr[k];
    }

    int jl = tid & 31;
    int pr = tid >> 5;
    int b0 = pr * 2, b1 = pr * 2 + 1;
    const float* wp = Ws + jl;
    unsigned target = 0;
    __syncthreads();

    for (int t = 0; t < SEQ; t++) {
        const float* hprev = (t == 0) ? (h0g + B0 * HID)
                                      : (g_outh + ((t - 1) * BATCH + B0) * HID);
        {
            float4* hd = (float4*)hs;
            const float4* hp = (const float4*)hprev;
            #pragma unroll
            for (int i = 0; i < 8; i++)
                hd[tid + i * 128] = hp[tid + i * 128];
        }
        __syncthreads();

        const float* xp = g_xproj + (t * BATCH + B0) * HID;
        float a0a = xp[b0 * HID + J0 + jl], a0b = 0.f;
        float a1a = xp[b1 * HID + J0 + jl], a1b = 0.f;
        const float* h0p = hs + b0 * HID;
        const float* h1p = hs + b1 * HID;

        #pragma unroll 2
        for (int k = 0; k < HID; k += 4) {
            float4 ha = *(const float4*)(h0p + k);
            float4 hb = *(const float4*)(h1p + k);
            float w0 = wp[(k + 0) * 32];
            float w1 = wp[(k + 1) * 32];
            float w2 = wp[(k + 2) * 32];
            float w3 = wp[(k + 3) * 32];
            a0a = fmaf(ha.x, w0, a0a);  a0b = fmaf(ha.y, w1, a0b);
            a0a = fmaf(ha.z, w2, a0a);  a0b = fmaf(ha.w, w3, a0b);
            a1a = fmaf(hb.x, w0, a1a);  a1b = fmaf(hb.y, w1, a1b);
            a1a = fmaf(hb.z, w2, a1a);  a1b = fmaf(hb.w, w3, a1b);
        }
        float r0 = tanhf(a0a + a0b);
        float r1 = tanhf(a1a + a1b);
        size_t gbase = (size_t)(t * BATCH + B0) * HID;
        int o0 = b0 * HID + J0 + jl;
        int o1 = b1 * HID + J0 + jl;
        g_outh[gbase + o0] = r0;
        g_outh[gbase + o1] = r1;
        __half h0h = __float2half_rn(r0);
        __half h1h = __float2half_rn(r1);
        g_Ahi[gbase + o0] = h0h;
        g_Ahi[gbase + o1] = h1h;
        g_Alo[gbase + o0] = __float2half_rn(r0 - __half2float(h0h));
        g_Alo[gbase + o1] = __float2half_rn(r1 - __half2float(h1h));

        __threadfence();
        __syncthreads();
        if (tid == 0) atomicAdd(&g_cnt[bg], 1u);
        target += 16;
        if (tid == 0) {
            unsigned v;
            do {
                asm volatile("ld.acquire.gpu.u32 %0, [%1];" : "=r"(v) : "l"(&g_cnt[bg]));
            } while (v < target);
        }
        __syncthreads();
    }
}

// ---------------- fp16 hi/lo split of W_fc ----------------
__global__ void k_splitB(const float* __restrict__ Wfc) {
    size_t i = (size_t)blockIdx.x * 256 + threadIdx.x;   // float4 index
    float4 v = ((const float4*)Wfc)[i];
    __half h0 = __float2half_rn(v.x);
    __half h1 = __float2half_rn(v.y);
    __half h2 = __float2half_rn(v.z);
    __half h3 = __float2half_rn(v.w);
    __half2* hi = (__half2*)g_Bhi;
    __half2* lo = (__half2*)g_Blo;
    hi[2 * i]     = __half2(h0, h1);
    hi[2 * i + 1] = __half2(h2, h3);
    lo[2 * i]     = __half2(__float2half_rn(v.x - __half2float(h0)),
                            __float2half_rn(v.y - __half2float(h1)));
    lo[2 * i + 1] = __half2(__float2half_rn(v.z - __half2float(h2)),
                            __float2half_rn(v.w - __half2float(h3)));
}

// ---------------- FC GEMM via mma.sync (fp16 x3 split, fp32 accum) ----------------
// C[m,v] = Ahi*Bhi + Alo*Bhi + Ahi*Blo ;  m = t*BATCH+b, out[b,t,v] += b_fc[v]
// CTA tile 128x128, 8 warps (2m x 4n), warp tile 64x32, k-tile 32, double buffered.
#define PITCH   40                     // halves per smem row (80 B, conflict-free)
#define TILEB   (128 * PITCH * 2)      // 10240 B per tile
#define STAGEB  (4 * TILEB)            // Ahi, Alo, Bhi, Blo

__global__ void __launch_bounds__(256, 1)
k_fcmma(const float* __restrict__ bfc, float* __restrict__ out) {
    extern __shared__ char dsm[];
    float* s_bias = (float*)dsm;                     // 128 floats
    uint32_t sbase = smem_u32(dsm) + 1024;           // tiles base

    int tid = threadIdx.x;
    int l = tid & 31, wid = tid >> 5;
    int m0 = blockIdx.x * 128;
    int v0 = blockIdx.y * 128;
    int mw = (wid >> 2) * 64;          // warp m offset: 0 / 64
    int nw = (wid & 3) * 32;           // warp n offset: 0/32/64/96

    if (tid < 128) s_bias[tid] = bfc[v0 + tid];

    const __half* gsrc[4] = { g_Ahi + (size_t)m0 * HID, g_Alo + (size_t)m0 * HID,
                              g_Bhi + (size_t)v0 * HID, g_Blo + (size_t)v0 * HID };

    // per-thread chunk decomposition for loading (8 chunks of 16B each)
    auto load_stage = [&](int s, int kt) {
        #pragma unroll
        for (int i = 0; i < 8; i++) {
            int id = tid + i * 256;          // 0..2047
            int tle = id >> 9;               // tile 0..3
            int c = id & 511;
            int r = c >> 2;                  // row 0..127
            int ch = c & 3;                  // 16B chunk 0..3
            uint32_t dst = sbase + s * STAGEB + tle * TILEB + r * 80 + ch * 16;
            cp16(dst, gsrc[tle] + (size_t)r * HID + kt * 32 + ch * 8);
        }
    };

    float acc[4][4][4];
    #pragma unroll
    for (int i = 0; i < 4; i++)
        #pragma unroll
        for (int j = 0; j < 4; j++)
            #pragma unroll
            for (int k = 0; k < 4; k++) acc[i][j][k] = 0.f;

    uint32_t aoff = (uint32_t)((mw + (l >> 2)) * 80 + (l & 3) * 4);
    uint32_t boff = (uint32_t)((nw + (l >> 2)) * 80 + (l & 3) * 4);

    load_stage(0, 0);
    CP_COMMIT();

    for (int kt = 0; kt < 16; kt++) {
        int buf = kt & 1;
        if (kt < 15) { load_stage(buf ^ 1, kt + 1); CP_COMMIT(); CP_WAIT(1); }
        else         { CP_WAIT(0); }
        __syncthreads();

        uint32_t sb = sbase + buf * STAGEB;
        #pragma unroll
        for (int ks = 0; ks < 2; ks++) {
            uint32_t ko = ks * 32;           // 16 halves = 32 B
            uint32_t ahi[4][4], alo[4][4], bhi[4][2], blo[4][2];
            #pragma unroll
            for (int fm = 0; fm < 4; fm++) {
                uint32_t ab = sb + aoff + fm * (16 * 80) + ko;
                ahi[fm][0] = lds32(ab);
                ahi[fm][1] = lds32(ab + 8 * 80);
                ahi[fm][2] = lds32(ab + 16);
                ahi[fm][3] = lds32(ab + 8 * 80 + 16);
            }
            #pragma unroll
            for (int fn = 0; fn < 4; fn++) {
                uint32_t bb = sb + 2 * TILEB + boff + fn * (8 * 80) + ko;
                bhi[fn][0] = lds32(bb);
                bhi[fn][1] = lds32(bb + 16);
            }
            #pragma unroll
            for (int fm = 0; fm < 4; fm++)
                #pragma unroll
                for (int fn = 0; fn < 4; fn++)
                    mma16816(acc[fm][fn], ahi[fm][0], ahi[fm][1], ahi[fm][2], ahi[fm][3],
                             bhi[fn][0], bhi[fn][1]);
            #pragma unroll
            for (int fn = 0; fn < 4; fn++) {
                uint32_t bb = sb + 3 * TILEB + boff + fn * (8 * 80) + ko;
                blo[fn][0] = lds32(bb);
                blo[fn][1] = lds32(bb + 16);
            }
            #pragma unroll
            for (int fm = 0; fm < 4; fm++)
                #pragma unroll
                for (int fn = 0; fn < 4; fn++)
                    mma16816(acc[fm][fn], ahi[fm][0], ahi[fm][1], ahi[fm][2], ahi[fm][3],
                             blo[fn][0], blo[fn][1]);
            #pragma unroll
            for (int fm = 0; fm < 4; fm++) {
                uint32_t ab = sb + TILEB + aoff + fm * (16 * 80) + ko;
                alo[fm][0] = lds32(ab);
                alo[fm][1] = lds32(ab + 8 * 80);
                alo[fm][2] = lds32(ab + 16);
                alo[fm][3] = lds32(ab + 8 * 80 + 16);
            }
            #pragma unroll
            for (int fm = 0; fm < 4; fm++)
                #pragma unroll
                for (int fn = 0; fn < 4; fn++)
                    mma16816(acc[fm][fn], alo[fm][0], alo[fm][1], alo[fm][2], alo[fm][3],
                             bhi[fn][0], bhi[fn][1]);
        }
        __syncthreads();
    }

    // epilogue: m = t*BATCH + b -> out[b*SEQ*VOCAB + t*VOCAB + v] + bias
    #pragma unroll
    for (int fm = 0; fm < 4; fm++) {
        #pragma unroll
        for (int fn = 0; fn < 4; fn++) {
            int vloc = nw + fn * 8 + (l & 3) * 2;
            float bv0 = s_bias[vloc];
            float bv1 = s_bias[vloc + 1];
            int m = m0 + mw + fm * 16 + (l >> 2);
            int b = m & (BATCH - 1);
            int t = m >> 6;
            float2* p = (float2*)(out + (size_t)b * SEQ * VOCAB + (size_t)t * VOCAB + v0 + vloc);
            *p = make_float2(acc[fm][fn][0] + bv0, acc[fm][fn][1] + bv1);
            int m2 = m + 8;
            b = m2 & (BATCH - 1);
            t = m2 >> 6;
            p = (float2*)(out + (size_t)b * SEQ * VOCAB + (size_t)t * VOCAB + v0 + vloc);
            *p = make_float2(acc[fm][fn][2] + bv0, acc[fm][fn][3] + bv1);
        }
    }
}

// ---------------- copy h_last ----------------
__global__ void k_hid(float* __restrict__ out) {
    int i = blockIdx.x * 256 + threadIdx.x;
    out[i] = g_outh[(SEQ - 1) * BATCH * HID + i];
}

// ---------------- launcher ----------------
extern "C" void kernel_launch(void* const* d_in, const int* in_sizes, int n_in,
                              void* d_out, int out_size) {
    const int*   inp = (const int*)d_in[0];
    const float* hid = (const float*)d_in[1];
    const float* Wih = (const float*)d_in[2];
    const float* Whh = (const float*)d_in[3];
    const float* bih = (const float*)d_in[4];
    const float* bhh = (const float*)d_in[5];
    const float* Wfc = (const float*)d_in[6];
    const float* bfc = (const float*)d_in[7];
    float* out = (float*)d_out;

    cudaFuncSetAttribute(k_rnn,   cudaFuncAttributeMaxDynamicSharedMemorySize, 81920);
    cudaFuncSetAttribute(k_fcmma, cudaFuncAttributeMaxDynamicSharedMemorySize, 1024 + 2 * STAGEB);

    k_transpose<<<dim3(VOCAB / 32, HID / 32), dim3(32, 8)>>>(Wih);
    k_gather<<<SEQ * BATCH, 128>>>(inp, bih, bhh);
    k_reset<<<1, 32>>>();
    k_splitB<<<(VOCAB * HID / 4) / 256, 256>>>(Wfc);
    k_rnn<<<128, 128, 81920>>>(Whh, hid);
    k_fcmma<<<dim3(MROWS / 128, VOCAB / 128), 256, 1024 + 2 * STAGEB>>>(bfc, out);

    long long logits_elems = (long long)BATCH * SEQ * VOCAB;
    if ((long long)out_size >= logits_elems + (long long)BATCH * HID) {
        k_hid<<<BATCH * HID / 256, 256>>>(out + logits_elems);
    }
}

// round 5
// speedup vs baseline: 1.5035x; 1.1330x over previous
#include <cuda_runtime.h>
#include <cuda_fp16.h>
#include <math.h>
#include <cstdint>

#define VOCAB 4096
#define HID   512
#define BATCH 64
#define SEQ   512
#define MROWS (SEQ * BATCH)

// ---------------- scratch (static device globals; no allocation) ----------------
__device__ float    g_WihT[VOCAB * HID];          // 8 MB  : W_ih transposed [V,H]
__device__ float    g_xproj[MROWS * HID];         // 64 MB : x_proj, layout [T,B,H]
__device__ float    g_outh [MROWS * HID];         // 64 MB : hidden states, layout [T,B,H]
__device__ __half   g_Ahi[MROWS * HID];           // 32 MB : fp16 hi of out_h
__device__ __half   g_Alo[MROWS * HID];           // 32 MB : fp16 lo of out_h
__device__ __half   g_B16[VOCAB * HID];           // 4 MB  : fp16 of W_fc
__device__ unsigned g_cnt[8];                     // per-batch-group barrier counters

// ======================= helpers =======================
__device__ __forceinline__ uint32_t smem_u32(const void* p) {
    uint32_t a;
    asm("{ .reg .u64 t; cvta.to.shared.u64 t, %1; cvt.u32.u64 %0, t; }" : "=r"(a) : "l"(p));
    return a;
}
__device__ __forceinline__ void cp16(uint32_t dst, const void* src) {
    asm volatile("cp.async.cg.shared.global [%0], [%1], 16;" :: "r"(dst), "l"(src));
}
#define CP_COMMIT() asm volatile("cp.async.commit_group;" ::: "memory")
#define CP_WAIT(n)  asm volatile("cp.async.wait_group %0;" :: "n"(n) : "memory")

__device__ __forceinline__ uint32_t lds32(uint32_t a) {
    uint32_t v;
    asm("ld.shared.b32 %0, [%1];" : "=r"(v) : "r"(a));
    return v;
}
__device__ __forceinline__ void mma16816(float* c, uint32_t a0, uint32_t a1,
                                         uint32_t a2, uint32_t a3,
                                         uint32_t b0, uint32_t b1) {
    asm volatile("mma.sync.aligned.m16n8k16.row.col.f32.f16.f16.f32 "
                 "{%0,%1,%2,%3}, {%4,%5,%6,%7}, {%8,%9}, {%0,%1,%2,%3};"
                 : "+f"(c[0]), "+f"(c[1]), "+f"(c[2]), "+f"(c[3])
                 : "r"(a0), "r"(a1), "r"(a2), "r"(a3), "r"(b0), "r"(b1));
}

// ---------------- transpose W_ih [H,V] -> g_WihT [V,H] ----------------
__global__ void k_transpose(const float* __restrict__ Wih) {
    __shared__ float tile[32][33];
    int v0 = blockIdx.x * 32;
    int h0 = blockIdx.y * 32;
    int tx = threadIdx.x, ty = threadIdx.y;   // 32 x 8
    #pragma unroll
    for (int i = ty; i < 32; i += 8)
        tile[i][tx] = Wih[(h0 + i) * VOCAB + v0 + tx];
    __syncthreads();
    #pragma unroll
    for (int i = ty; i < 32; i += 8)
        g_WihT[(v0 + i) * HID + h0 + tx] = tile[tx][i];
}

// ---------------- gather + bias ----------------
__global__ void k_gather(const int* __restrict__ inp,
                         const float* __restrict__ b_ih,
                         const float* __restrict__ b_hh) {
    int row = blockIdx.x;              // row = t*BATCH + b
    int t = row / BATCH;
    int b = row % BATCH;
    int tok = inp[b * SEQ + t];
    const float4* src = (const float4*)&g_WihT[tok * HID];
    const float4* bi4 = (const float4*)b_ih;
    const float4* bh4 = (const float4*)b_hh;
    float4* dst = (float4*)&g_xproj[row * HID];
    int i = threadIdx.x;               // 128 threads
    float4 v = src[i];
    float4 bi = bi4[i], bh = bh4[i];
    v.x += bi.x + bh.x;  v.y += bi.y + bh.y;
    v.z += bi.z + bh.z;  v.w += bi.w + bh.w;
    dst[i] = v;
}

__global__ void k_reset() {
    if (threadIdx.x < 8) g_cnt[threadIdx.x] = 0;
}

// ---------------- recurrence (+ fused fp16 hi/lo split of h) ----------------
extern "C" __global__ void __launch_bounds__(128, 1)
k_rnn(const float* __restrict__ Whh, const float* __restrict__ h0g) {
    extern __shared__ float smem[];
    float* Ws = smem;                 // [k][j] : 512*32
    float* hs = smem + 512 * 32;      // [b][k] : 8*512

    int bx = blockIdx.x;
    int bg = bx & 7;
    int jg = bx >> 3;
    int B0 = bg * 8;
    int J0 = jg * 32;
    int tid = threadIdx.x;

    for (int j = 0; j < 32; j++) {
        const float* wr = Whh + (J0 + j) * HID;
        for (int k = tid; k < HID; k += 128)
            Ws[k * 32 + j] = wr[k];
    }

    int jl = tid & 31;
    int pr = tid >> 5;
    int b0 = pr * 2, b1 = pr * 2 + 1;
    const float* wp = Ws + jl;
    unsigned target = 0;
    __syncthreads();

    for (int t = 0; t < SEQ; t++) {
        const float* hprev = (t == 0) ? (h0g + B0 * HID)
                                      : (g_outh + ((t - 1) * BATCH + B0) * HID);
        {
            float4* hd = (float4*)hs;
            const float4* hp = (const float4*)hprev;
            #pragma unroll
            for (int i = 0; i < 8; i++)
                hd[tid + i * 128] = hp[tid + i * 128];
        }
        __syncthreads();

        const float* xp = g_xproj + (t * BATCH + B0) * HID;
        float a0a = xp[b0 * HID + J0 + jl], a0b = 0.f;
        float a1a = xp[b1 * HID + J0 + jl], a1b = 0.f;
        const float* h0p = hs + b0 * HID;
        const float* h1p = hs + b1 * HID;

        #pragma unroll 2
        for (int k = 0; k < HID; k += 4) {
            float4 ha = *(const float4*)(h0p + k);
            float4 hb = *(const float4*)(h1p + k);
            float w0 = wp[(k + 0) * 32];
            float w1 = wp[(k + 1) * 32];
            float w2 = wp[(k + 2) * 32];
            float w3 = wp[(k + 3) * 32];
            a0a = fmaf(ha.x, w0, a0a);  a0b = fmaf(ha.y, w1, a0b);
            a0a = fmaf(ha.z, w2, a0a);  a0b = fmaf(ha.w, w3, a0b);
            a1a = fmaf(hb.x, w0, a1a);  a1b = fmaf(hb.y, w1, a1b);
            a1a = fmaf(hb.z, w2, a1a);  a1b = fmaf(hb.w, w3, a1b);
        }
        float r0 = tanhf(a0a + a0b);
        float r1 = tanhf(a1a + a1b);
        size_t gbase = (size_t)(t * BATCH + B0) * HID;
        int o0 = b0 * HID + J0 + jl;
        int o1 = b1 * HID + J0 + jl;
        g_outh[gbase + o0] = r0;
        g_outh[gbase + o1] = r1;
        __half h0h = __float2half_rn(r0);
        __half h1h = __float2half_rn(r1);
        g_Ahi[gbase + o0] = h0h;
        g_Ahi[gbase + o1] = h1h;
        g_Alo[gbase + o0] = __float2half_rn(r0 - __half2float(h0h));
        g_Alo[gbase + o1] = __float2half_rn(r1 - __half2float(h1h));

        __threadfence();
        __syncthreads();
        if (tid == 0) atomicAdd(&g_cnt[bg], 1u);
        target += 16;
        if (tid == 0) {
            unsigned v;
            do {
                asm volatile("ld.acquire.gpu.u32 %0, [%1];" : "=r"(v) : "l"(&g_cnt[bg]));
            } while (v < target);
        }
        __syncthreads();
    }
}

// ---------------- fp16 convert of W_fc ----------------
__global__ void k_convB(const float* __restrict__ Wfc) {
    size_t i = (size_t)blockIdx.x * 256 + threadIdx.x;   // float4 index
    float4 v = ((const float4*)Wfc)[i];
    __half2* hi = (__half2*)g_B16;
    hi[2 * i]     = __half2(__float2half_rn(v.x), __float2half_rn(v.y));
    hi[2 * i + 1] = __half2(__float2half_rn(v.z), __float2half_rn(v.w));
}

// ---------------- FC GEMM via mma.sync: C = (Ahi + Alo) * B16^T ----------------
// CTA tile 128x128, 8 warps (2m x 4n), warp tile 64x32, k-tile 32, double buffered,
// 2 CTAs/SM. B fragments shared across both passes.
#define PITCH   40                     // halves per smem row (80 B, conflict-free)
#define TILEB   (128 * PITCH * 2)      // 10240 B per tile
#define STAGEB  (3 * TILEB)            // Ahi, Alo, B

__global__ void __launch_bounds__(256, 2)
k_fcmma(const float* __restrict__ bfc, float* __restrict__ out) {
    extern __shared__ char dsm[];
    float* s_bias = (float*)dsm;                     // 128 floats
    uint32_t sbase = smem_u32(dsm) + 1024;           // tiles base

    int tid = threadIdx.x;
    int l = tid & 31, wid = tid >> 5;
    int m0 = blockIdx.x * 128;
    int v0 = blockIdx.y * 128;
    int mw = (wid >> 2) * 64;          // warp m offset: 0 / 64
    int nw = (wid & 3) * 32;           // warp n offset: 0/32/64/96

    if (tid < 128) s_bias[tid] = bfc[v0 + tid];

    const __half* gsrc[3] = { g_Ahi + (size_t)m0 * HID, g_Alo + (size_t)m0 * HID,
                              g_B16 + (size_t)v0 * HID };

    // 3 tiles x 512 16B-chunks = 1536 chunks; 6 per thread
    auto load_stage = [&](int s, int kt) {
        #pragma unroll
        for (int i = 0; i < 6; i++) {
            int id = tid + i * 256;          // 0..1535
            int tle = id >> 9;               // tile 0..2
            int c = id & 511;
            int r = c >> 2;                  // row 0..127
            int ch = c & 3;                  // 16B chunk 0..3
            uint32_t dst = sbase + s * STAGEB + tle * TILEB + r * 80 + ch * 16;
            cp16(dst, gsrc[tle] + (size_t)r * HID + kt * 32 + ch * 8);
        }
    };

    float acc[4][4][4];
    #pragma unroll
    for (int i = 0; i < 4; i++)
        #pragma unroll
        for (int j = 0; j < 4; j++)
            #pragma unroll
            for (int k = 0; k < 4; k++) acc[i][j][k] = 0.f;

    uint32_t aoff = (uint32_t)((mw + (l >> 2)) * 80 + (l & 3) * 4);
    uint32_t boff = (uint32_t)((nw + (l >> 2)) * 80 + (l & 3) * 4);

    load_stage(0, 0);
    CP_COMMIT();

    for (int kt = 0; kt < 16; kt++) {
        int buf = kt & 1;
        if (kt < 15) { load_stage(buf ^ 1, kt + 1); CP_COMMIT(); CP_WAIT(1); }
        else         { CP_WAIT(0); }
        __syncthreads();

        uint32_t sb = sbase + buf * STAGEB;
        #pragma unroll
        for (int ks = 0; ks < 2; ks++) {
            uint32_t ko = ks * 32;           // 16 halves = 32 B
            uint32_t bf[4][2];
            #pragma unroll
            for (int fn = 0; fn < 4; fn++) {
                uint32_t bb = sb + 2 * TILEB + boff + fn * (8 * 80) + ko;
                bf[fn][0] = lds32(bb);
                bf[fn][1] = lds32(bb + 16);
            }
            {
                uint32_t af[4][4];
                #pragma unroll
                for (int fm = 0; fm < 4; fm++) {
                    uint32_t ab = sb + aoff + fm * (16 * 80) + ko;
                    af[fm][0] = lds32(ab);
                    af[fm][1] = lds32(ab + 8 * 80);
                    af[fm][2] = lds32(ab + 16);
                    af[fm][3] = lds32(ab + 8 * 80 + 16);
                }
                #pragma unroll
                for (int fm = 0; fm < 4; fm++)
                    #pragma unroll
                    for (int fn = 0; fn < 4; fn++)
                        mma16816(acc[fm][fn], af[fm][0], af[fm][1], af[fm][2], af[fm][3],
                                 bf[fn][0], bf[fn][1]);
            }
            {
                uint32_t af[4][4];
                #pragma unroll
                for (int fm = 0; fm < 4; fm++) {
                    uint32_t ab = sb + TILEB + aoff + fm * (16 * 80) + ko;
                    af[fm][0] = lds32(ab);
                    af[fm][1] = lds32(ab + 8 * 80);
                    af[fm][2] = lds32(ab + 16);
                    af[fm][3] = lds32(ab + 8 * 80 + 16);
                }
                #pragma unroll
                for (int fm = 0; fm < 4; fm++)
                    #pragma unroll
                    for (int fn = 0; fn < 4; fn++)
                        mma16816(acc[fm][fn], af[fm][0], af[fm][1], af[fm][2], af[fm][3],
                                 bf[fn][0], bf[fn][1]);
            }
        }
        __syncthreads();
    }

    // epilogue: m = t*BATCH + b -> out[b*SEQ*VOCAB + t*VOCAB + v] + bias
    #pragma unroll
    for (int fm = 0; fm < 4; fm++) {
        #pragma unroll
        for (int fn = 0; fn < 4; fn++) {
            int vloc = nw + fn * 8 + (l & 3) * 2;
            float bv0 = s_bias[vloc];
            float bv1 = s_bias[vloc + 1];
            int m = m0 + mw + fm * 16 + (l >> 2);
            int b = m & (BATCH - 1);
            int t = m >> 6;
            float2* p = (float2*)(out + (size_t)b * SEQ * VOCAB + (size_t)t * VOCAB + v0 + vloc);
            *p = make_float2(acc[fm][fn][0] + bv0, acc[fm][fn][1] + bv1);
            int m2 = m + 8;
            b = m2 & (BATCH - 1);
            t = m2 >> 6;
            p = (float2*)(out + (size_t)b * SEQ * VOCAB + (size_t)t * VOCAB + v0 + vloc);
            *p = make_float2(acc[fm][fn][2] + bv0, acc[fm][fn][3] + bv1);
        }
    }
}

// ---------------- copy h_last ----------------
__global__ void k_hid(float* __restrict__ out) {
    int i = blockIdx.x * 256 + threadIdx.x;
    out[i] = g_outh[(SEQ - 1) * BATCH * HID + i];
}

// ---------------- launcher ----------------
extern "C" void kernel_launch(void* const* d_in, const int* in_sizes, int n_in,
                              void* d_out, int out_size) {
    const int*   inp = (const int*)d_in[0];
    const float* hid = (const float*)d_in[1];
    const float* Wih = (const float*)d_in[2];
    const float* Whh = (const float*)d_in[3];
    const float* bih = (const float*)d_in[4];
    const float* bhh = (const float*)d_in[5];
    const float* Wfc = (const float*)d_in[6];
    const float* bfc = (const float*)d_in[7];
    float* out = (float*)d_out;

    cudaFuncSetAttribute(k_rnn,   cudaFuncAttributeMaxDynamicSharedMemorySize, 81920);
    cudaFuncSetAttribute(k_fcmma, cudaFuncAttributeMaxDynamicSharedMemorySize, 1024 + 2 * STAGEB);

    // k_rnn placed 4th: that's the launch the profiler has been catching.
    k_transpose<<<dim3(VOCAB / 32, HID / 32), dim3(32, 8)>>>(Wih);
    k_gather<<<SEQ * BATCH, 128>>>(inp, bih, bhh);
    k_reset<<<1, 32>>>();
    k_rnn<<<128, 128, 81920>>>(Whh, hid);
    k_convB<<<(VOCAB * HID / 4) / 256, 256>>>(Wfc);
    k_fcmma<<<dim3(MROWS / 128, VOCAB / 128), 256, 1024 + 2 * STAGEB>>>(bfc, out);

    long long logits_elems = (long long)BATCH * SEQ * VOCAB;
    if ((long long)out_size >= logits_elems + (long long)BATCH * HID) {
        k_hid<<<BATCH * HID / 256, 256>>>(out + logits_elems);
    }
}

// round 6
// speedup vs baseline: 1.9035x; 1.2660x over previous
#include <cuda_runtime.h>
#include <cuda_fp16.h>
#include <math.h>
#include <cstdint>

#define VOCAB 4096
#define HID   512
#define BATCH 64
#define SEQ   512
#define MROWS (SEQ * BATCH)

// ---------------- scratch (static device globals; no allocation) ----------------
__device__ float    g_WihT[VOCAB * HID];          // 8 MB  : W_ih transposed [V,H]
__device__ float    g_xproj[MROWS * HID];         // 64 MB : x_proj, layout [T,B,H]
__device__ float2   g_hseq[SEQ * 8 * 4 * 512];    // 64 MB : h states, pair-interleaved [t][bg][pair][j]
__device__ __half   g_Ahi[MROWS * HID];           // 32 MB : fp16 hi of out_h
__device__ __half   g_Alo[MROWS * HID];           // 32 MB : fp16 lo of out_h
__device__ __half   g_B16[VOCAB * HID];           // 4 MB  : fp16 of W_fc
__device__ unsigned g_cnt[8];                     // per-batch-group barrier counters

// ======================= helpers =======================
__device__ __forceinline__ uint32_t smem_u32(const void* p) {
    uint32_t a;
    asm("{ .reg .u64 t; cvta.to.shared.u64 t, %1; cvt.u32.u64 %0, t; }" : "=r"(a) : "l"(p));
    return a;
}
__device__ __forceinline__ void cp16(uint32_t dst, const void* src) {
    asm volatile("cp.async.cg.shared.global [%0], [%1], 16;" :: "r"(dst), "l"(src));
}
#define CP_COMMIT() asm volatile("cp.async.commit_group;" ::: "memory")
#define CP_WAIT(n)  asm volatile("cp.async.wait_group %0;" :: "n"(n) : "memory")

__device__ __forceinline__ void ldm_x4(uint32_t& r0, uint32_t& r1, uint32_t& r2,
                                       uint32_t& r3, uint32_t a) {
    asm volatile("ldmatrix.sync.aligned.m8n8.x4.shared.b16 {%0,%1,%2,%3}, [%4];"
                 : "=r"(r0), "=r"(r1), "=r"(r2), "=r"(r3) : "r"(a));
}
__device__ __forceinline__ void mma16816(float* c, uint32_t a0, uint32_t a1,
                                         uint32_t a2, uint32_t a3,
                                         uint32_t b0, uint32_t b1) {
    asm volatile("mma.sync.aligned.m16n8k16.row.col.f32.f16.f16.f32 "
                 "{%0,%1,%2,%3}, {%4,%5,%6,%7}, {%8,%9}, {%0,%1,%2,%3};"
                 : "+f"(c[0]), "+f"(c[1]), "+f"(c[2]), "+f"(c[3])
                 : "r"(a0), "r"(a1), "r"(a2), "r"(a3), "r"(b0), "r"(b1));
}

// ---------------- transpose W_ih [H,V] -> g_WihT [V,H] ----------------
__global__ void k_transpose(const float* __restrict__ Wih) {
    __shared__ float tile[32][33];
    int v0 = blockIdx.x * 32;
    int h0 = blockIdx.y * 32;
    int tx = threadIdx.x, ty = threadIdx.y;   // 32 x 8
    #pragma unroll
    for (int i = ty; i < 32; i += 8)
        tile[i][tx] = Wih[(h0 + i) * VOCAB + v0 + tx];
    __syncthreads();
    #pragma unroll
    for (int i = ty; i < 32; i += 8)
        g_WihT[(v0 + i) * HID + h0 + tx] = tile[tx][i];
}

// ---------------- gather + bias ----------------
__global__ void k_gather(const int* __restrict__ inp,
                         const float* __restrict__ b_ih,
                         const float* __restrict__ b_hh) {
    int row = blockIdx.x;              // row = t*BATCH + b
    int t = row / BATCH;
    int b = row % BATCH;
    int tok = inp[b * SEQ + t];
    const float4* src = (const float4*)&g_WihT[tok * HID];
    const float4* bi4 = (const float4*)b_ih;
    const float4* bh4 = (const float4*)b_hh;
    float4* dst = (float4*)&g_xproj[row * HID];
    int i = threadIdx.x;               // 128 threads
    float4 v = src[i];
    float4 bi = bi4[i], bh = bh4[i];
    v.x += bi.x + bh.x;  v.y += bi.y + bh.y;
    v.z += bi.z + bh.z;  v.w += bi.w + bh.w;
    dst[i] = v;
}

__global__ void k_reset() {
    if (threadIdx.x < 8) g_cnt[threadIdx.x] = 0;
}

// ---------------- recurrence v2: warp K-split + smem reduction ----------------
// 128 CTAs = 8 batch-groups x 16 j-slices(32). 128 threads = 4 warps, each warp
// owns k-range [w*128, w*128+128) for ALL 8 batches (4 pairs).
// smem: Ws[512][32] 64KB + hp[4][512] float2 16KB + part[4][4][32] float2 4KB = 84KB
extern "C" __global__ void __launch_bounds__(128, 1)
k_rnn(const float* __restrict__ Whh, const float* __restrict__ h0g) {
    extern __shared__ float sm[];
    float*  Ws   = sm;                          // [k][j] 512*32
    float2* hp   = (float2*)(sm + 512 * 32);    // [pair][k] 4*512
    float2* part = hp + 4 * 512;                // [warp][pair][jl]

    int bx = blockIdx.x;
    int bg = bx & 7;
    int jg = bx >> 3;
    int B0 = bg * 8;
    int J0 = jg * 32;
    int tid = threadIdx.x;
    int w = tid >> 5, jl = tid & 31;
    int kbase = w * 128;

    // load W_hh slice [k][j]
    for (int j = 0; j < 32; j++) {
        const float* wr = Whh + (J0 + j) * HID;
        for (int k = tid; k < HID; k += 128)
            Ws[k * 32 + j] = wr[k];
    }
    __syncthreads();

    unsigned target = 0;
    for (int t = 0; t < SEQ; t++) {
        // ---- stage h_{t-1} pair-interleaved into smem ----
        if (t == 0) {
            for (int idx = tid; idx < 2048; idx += 128) {
                int p = idx >> 9, k = idx & 511;
                hp[p * 512 + k] = make_float2(h0g[(B0 + 2 * p) * HID + k],
                                              h0g[(B0 + 2 * p + 1) * HID + k]);
            }
        } else {
            const float4* src = (const float4*)&g_hseq[((size_t)(t - 1) * 8 + bg) * 2048];
            float4* dst = (float4*)hp;
            #pragma unroll
            for (int i = 0; i < 8; i++)
                dst[tid + i * 128] = src[tid + i * 128];
        }
        __syncthreads();

        // ---- partial dot products over this warp's k-range ----
        float2 accA[4], accB[4];
        #pragma unroll
        for (int p = 0; p < 4; p++) {
            accA[p] = make_float2(0.f, 0.f);
            accB[p] = make_float2(0.f, 0.f);
        }
        const float* wptr = Ws + jl + kbase * 32;
        const float4* h4 = ((const float4*)hp) + (kbase >> 1);
        #pragma unroll 2
        for (int i = 0; i < 64; i++) {
            float w0 = wptr[0], w1 = wptr[32];
            #pragma unroll
            for (int p = 0; p < 4; p++) {
                float4 hv = h4[p * 256];        // (b0[k], b1[k], b0[k+1], b1[k+1]) broadcast
                accA[p].x = fmaf(hv.x, w0, accA[p].x);
                accA[p].y = fmaf(hv.y, w0, accA[p].y);
                accB[p].x = fmaf(hv.z, w1, accB[p].x);
                accB[p].y = fmaf(hv.w, w1, accB[p].y);
            }
            wptr += 64;
            h4 += 1;
        }
        #pragma unroll
        for (int p = 0; p < 4; p++)
            part[(w * 4 + p) * 32 + jl] = make_float2(accA[p].x + accB[p].x,
                                                      accA[p].y + accB[p].y);
        __syncthreads();

        // ---- reduce across 4 warps, tanh, store ----
        {
            int p = tid >> 5, j2 = tid & 31;
            float2 s0 = part[(0 + p) * 32 + j2];
            float2 s1 = part[(4 + p) * 32 + j2];
            float2 s2 = part[(8 + p) * 32 + j2];
            float2 s3 = part[(12 + p) * 32 + j2];
            float sx = (s0.x + s1.x) + (s2.x + s3.x);
            float sy = (s0.y + s1.y) + (s2.y + s3.y);
            int b0g = B0 + 2 * p;
            size_t xb = ((size_t)t * BATCH + b0g) * HID + J0 + j2;
            float r0 = tanhf(sx + g_xproj[xb]);
            float r1 = tanhf(sy + g_xproj[xb + HID]);
            g_hseq[((size_t)(t * 8 + bg) * 4 + p) * 512 + (J0 + j2)] = make_float2(r0, r1);
            __half hh0 = __float2half_rn(r0);
            __half hh1 = __float2half_rn(r1);
            g_Ahi[xb]       = hh0;
            g_Ahi[xb + HID] = hh1;
            g_Alo[xb]       = __float2half_rn(r0 - __half2float(hh0));
            g_Alo[xb + HID] = __float2half_rn(r1 - __half2float(hh1));
        }
        __syncthreads();

        // ---- group barrier (16 CTAs): release-arrive + acquire-poll ----
        if (t < SEQ - 1) {
            target += 16;
            if (tid == 0) {
                asm volatile("fence.acq_rel.gpu;" ::: "memory");
                asm volatile("red.relaxed.gpu.global.add.u32 [%0], %1;"
                             :: "l"(&g_cnt[bg]), "r"(1u) : "memory");
                unsigned v;
                do {
                    asm volatile("ld.acquire.gpu.global.u32 %0, [%1];"
                                 : "=r"(v) : "l"(&g_cnt[bg]));
                } while (v < target);
            }
            __syncthreads();
        }
    }
}

// ---------------- fp16 convert of W_fc ----------------
__global__ void k_convB(const float* __restrict__ Wfc) {
    size_t i = (size_t)blockIdx.x * 256 + threadIdx.x;   // float4 index
    float4 v = ((const float4*)Wfc)[i];
    __half2* hi = (__half2*)g_B16;
    hi[2 * i]     = __half2(__float2half_rn(v.x), __float2half_rn(v.y));
    hi[2 * i + 1] = __half2(__float2half_rn(v.z), __float2half_rn(v.w));
}

// ---------------- FC GEMM via mma.sync: C = (Ahi + Alo) * B16^T ----------------
// CTA tile 128x128, 8 warps (2m x 4n), warp tile 64x32, k-tile 32, double buffered,
// 2 CTAs/SM, ldmatrix fragment loads.
#define PITCH   40                     // halves per smem row (80 B, conflict-free)
#define TILEB   (128 * PITCH * 2)      // 10240 B per tile
#define STAGEB  (3 * TILEB)            // Ahi, Alo, B

__global__ void __launch_bounds__(256, 2)
k_fcmma(const float* __restrict__ bfc, float* __restrict__ out) {
    extern __shared__ char dsm[];
    float* s_bias = (float*)dsm;                     // 128 floats
    uint32_t sbase = smem_u32(dsm) + 1024;           // tiles base

    int tid = threadIdx.x;
    int l = tid & 31, wid = tid >> 5;
    int m0 = blockIdx.x * 128;
    int v0 = blockIdx.y * 128;
    int mw = (wid >> 2) * 64;          // warp m offset: 0 / 64
    int nw = (wid & 3) * 32;           // warp n offset: 0/32/64/96

    if (tid < 128) s_bias[tid] = bfc[v0 + tid];

    const __half* gsrc[3] = { g_Ahi + (size_t)m0 * HID, g_Alo + (size_t)m0 * HID,
                              g_B16 + (size_t)v0 * HID };

    auto load_stage = [&](int s, int kt) {
        #pragma unroll
        for (int i = 0; i < 6; i++) {
            int id = tid + i * 256;          // 0..1535
            int tle = id >> 9;               // tile 0..2
            int c = id & 511;
            int r = c >> 2;                  // row 0..127
            int ch = c & 3;                  // 16B chunk 0..3
            uint32_t dst = sbase + s * STAGEB + tle * TILEB + r * 80 + ch * 16;
            cp16(dst, gsrc[tle] + (size_t)r * HID + kt * 32 + ch * 8);
        }
    };

    float acc[4][4][4];
    #pragma unroll
    for (int i = 0; i < 4; i++)
        #pragma unroll
        for (int j = 0; j < 4; j++)
            #pragma unroll
            for (int k = 0; k < 4; k++) acc[i][j][k] = 0.f;

    // ldmatrix lane addressing
    int mat = l >> 3, r8 = l & 7;
    uint32_t a_lane = (uint32_t)((mw + (mat & 1) * 8 + r8) * 80 + (mat >> 1) * 16);
    uint32_t b_lane = (uint32_t)((nw + (mat >> 1) * 8 + r8) * 80 + (mat & 1) * 16) + 2 * TILEB;

    load_stage(0, 0);
    CP_COMMIT();

    for (int kt = 0; kt < 16; kt++) {
        int buf = kt & 1;
        if (kt < 15) { load_stage(buf ^ 1, kt + 1); CP_COMMIT(); CP_WAIT(1); }
        else         { CP_WAIT(0); }
        __syncthreads();

        uint32_t sb = sbase + buf * STAGEB;
        #pragma unroll
        for (int ks = 0; ks < 2; ks++) {
            uint32_t ko = ks * 32;           // 16 halves = 32 B
            uint32_t bf[4][2];
            ldm_x4(bf[0][0], bf[0][1], bf[1][0], bf[1][1], sb + b_lane + ko);
            ldm_x4(bf[2][0], bf[2][1], bf[3][0], bf[3][1], sb + b_lane + 16 * 80 + ko);
            {
                uint32_t af[4][4];
                #pragma unroll
                for (int fm = 0; fm < 4; fm++)
                    ldm_x4(af[fm][0], af[fm][1], af[fm][2], af[fm][3],
                           sb + a_lane + fm * (16 * 80) + ko);
                #pragma unroll
                for (int fm = 0; fm < 4; fm++)
                    #pragma unroll
                    for (int fn = 0; fn < 4; fn++)
                        mma16816(acc[fm][fn], af[fm][0], af[fm][1], af[fm][2], af[fm][3],
                                 bf[fn][0], bf[fn][1]);
            }
            {
                uint32_t af[4][4];
                #pragma unroll
                for (int fm = 0; fm < 4; fm++)
                    ldm_x4(af[fm][0], af[fm][1], af[fm][2], af[fm][3],
                           sb + TILEB + a_lane + fm * (16 * 80) + ko);
                #pragma unroll
                for (int fm = 0; fm < 4; fm++)
                    #pragma unroll
                    for (int fn = 0; fn < 4; fn++)
                        mma16816(acc[fm][fn], af[fm][0], af[fm][1], af[fm][2], af[fm][3],
                                 bf[fn][0], bf[fn][1]);
            }
        }
        __syncthreads();
    }

    // epilogue: m = t*BATCH + b -> out[b*SEQ*VOCAB + t*VOCAB + v] + bias
    #pragma unroll
    for (int fm = 0; fm < 4; fm++) {
        #pragma unroll
        for (int fn = 0; fn < 4; fn++) {
            int vloc = nw + fn * 8 + (l & 3) * 2;
            float bv0 = s_bias[vloc];
            float bv1 = s_bias[vloc + 1];
            int m = m0 + mw + fm * 16 + (l >> 2);
            int b = m & (BATCH - 1);
            int t = m >> 6;
            float2* p = (float2*)(out + (size_t)b * SEQ * VOCAB + (size_t)t * VOCAB + v0 + vloc);
            *p = make_float2(acc[fm][fn][0] + bv0, acc[fm][fn][1] + bv1);
            int m2 = m + 8;
            b = m2 & (BATCH - 1);
            t = m2 >> 6;
            p = (float2*)(out + (size_t)b * SEQ * VOCAB + (size_t)t * VOCAB + v0 + vloc);
            *p = make_float2(acc[fm][fn][2] + bv0, acc[fm][fn][3] + bv1);
        }
    }
}

// ---------------- copy h_last from g_hseq[t=511] ----------------
__global__ void k_hid(float* __restrict__ out) {
    int i = blockIdx.x * 256 + threadIdx.x;   // i = b*HID + h
    int b = i >> 9, h = i & 511;
    int bg = b >> 3, p = (b & 7) >> 1, e = b & 1;
    float2 v = g_hseq[((size_t)(511 * 8 + bg) * 4 + p) * 512 + h];
    out[i] = e ? v.y : v.x;
}

// ---------------- launcher ----------------
extern "C" void kernel_launch(void* const* d_in, const int* in_sizes, int n_in,
                              void* d_out, int out_size) {
    const int*   inp = (const int*)d_in[0];
    const float* hid = (const float*)d_in[1];
    const float* Wih = (const float*)d_in[2];
    const float* Whh = (const float*)d_in[3];
    const float* bih = (const float*)d_in[4];
    const float* bhh = (const float*)d_in[5];
    const float* Wfc = (const float*)d_in[6];
    const float* bfc = (const float*)d_in[7];
    float* out = (float*)d_out;

    cudaFuncSetAttribute(k_rnn,   cudaFuncAttributeMaxDynamicSharedMemorySize, 86016);
    cudaFuncSetAttribute(k_fcmma, cudaFuncAttributeMaxDynamicSharedMemorySize, 1024 + 2 * STAGEB);

    // launch order chosen so ncu (-s 5 -c 1) profiles k_fcmma (#6)
    k_transpose<<<dim3(VOCAB / 32, HID / 32), dim3(32, 8)>>>(Wih);
    k_gather<<<SEQ * BATCH, 128>>>(inp, bih, bhh);
    k_reset<<<1, 32>>>();
    k_convB<<<(VOCAB * HID / 4) / 256, 256>>>(Wfc);
    k_rnn<<<128, 128, 86016>>>(Whh, hid);
    k_fcmma<<<dim3(MROWS / 128, VOCAB / 128), 256, 1024 + 2 * STAGEB>>>(bfc, out);

    long long logits_elems = (long long)BATCH * SEQ * VOCAB;
    if ((long long)out_size >= logits_elems + (long long)BATCH * HID) {
        k_hid<<<BATCH * HID / 256, 256>>>(out + logits_elems);
    }
}

// round 8
// speedup vs baseline: 2.2188x; 1.1656x over previous
#include <cuda_runtime.h>
#include <cuda_fp16.h>
#include <math.h>
#include <cstdint>

#define VOCAB 4096
#define HID   512
#define BATCH 64
#define SEQ   512
#define MROWS (SEQ * BATCH)

typedef unsigned long long u64;

// ---------------- scratch (static device globals; no allocation) ----------------
__device__ float    g_WihT[VOCAB * HID];          // 8 MB  : W_ih transposed [V,H]
__device__ float    g_xproj[MROWS * HID];         // 64 MB : x_proj, layout [T,B,H]
__device__ float2   g_hseq[SEQ * 8 * 4 * 512];    // 64 MB : h states, pair-interleaved
__device__ __half   g_A16[MROWS * HID];           // 32 MB : fp16 of out_h
__device__ __half   g_B16[VOCAB * HID];           // 4 MB  : fp16 of W_fc
__device__ unsigned g_cnt[8];                     // per-batch-group barrier counters

// ======================= helpers =======================
__device__ __forceinline__ uint32_t smem_u32(const void* p) {
    uint32_t a;
    asm("{ .reg .u64 t; cvta.to.shared.u64 t, %1; cvt.u32.u64 %0, t; }" : "=r"(a) : "l"(p));
    return a;
}
__device__ __forceinline__ void cp16(uint32_t dst, const void* src) {
    asm volatile("cp.async.cg.shared.global [%0], [%1], 16;" :: "r"(dst), "l"(src));
}
#define CP_COMMIT() asm volatile("cp.async.commit_group;" ::: "memory")
#define CP_WAIT(n)  asm volatile("cp.async.wait_group %0;" :: "n"(n) : "memory")

__device__ __forceinline__ void ldm_x4(uint32_t& r0, uint32_t& r1, uint32_t& r2,
                                       uint32_t& r3, uint32_t a) {
    asm volatile("ldmatrix.sync.aligned.m8n8.x4.shared.b16 {%0,%1,%2,%3}, [%4];"
                 : "=r"(r0), "=r"(r1), "=r"(r2), "=r"(r3) : "r"(a));
}
__device__ __forceinline__ void mma16816(float* c, uint32_t a0, uint32_t a1,
                                         uint32_t a2, uint32_t a3,
                                         uint32_t b0, uint32_t b1) {
    asm volatile("mma.sync.aligned.m16n8k16.row.col.f32.f16.f16.f32 "
                 "{%0,%1,%2,%3}, {%4,%5,%6,%7}, {%8,%9}, {%0,%1,%2,%3};"
                 : "+f"(c[0]), "+f"(c[1]), "+f"(c[2]), "+f"(c[3])
                 : "r"(a0), "r"(a1), "r"(a2), "r"(a3), "r"(b0), "r"(b1));
}

// ---- packed fp32x2 (sm_100+ baseline PTX) ----
__device__ __forceinline__ u64 pack2(float x, float y) {
    u64 r; asm("mov.b64 %0, {%1, %2};" : "=l"(r) : "f"(x), "f"(y)); return r;
}
__device__ __forceinline__ float2 unpack2(u64 v) {
    float2 f; asm("mov.b64 {%0, %1}, %2;" : "=f"(f.x), "=f"(f.y) : "l"(v)); return f;
}
__device__ __forceinline__ void fma2(u64& acc, u64 a, u64 b) {
    asm("fma.rn.f32x2 %0, %1, %2, %0;" : "+l"(acc) : "l"(a), "l"(b));
}
__device__ __forceinline__ u64 add2(u64 a, u64 b) {
    u64 r; asm("add.rn.f32x2 %0, %1, %2;" : "=l"(r) : "l"(a), "l"(b)); return r;
}

// ---------------- transpose W_ih [H,V] -> g_WihT [V,H] ----------------
__global__ void k_transpose(const float* __restrict__ Wih) {
    __shared__ float tile[32][33];
    int v0 = blockIdx.x * 32;
    int h0 = blockIdx.y * 32;
    int tx = threadIdx.x, ty = threadIdx.y;   // 32 x 8
    #pragma unroll
    for (int i = ty; i < 32; i += 8)
        tile[i][tx] = Wih[(h0 + i) * VOCAB + v0 + tx];
    __syncthreads();
    #pragma unroll
    for (int i = ty; i < 32; i += 8)
        g_WihT[(v0 + i) * HID + h0 + tx] = tile[tx][i];
}

// ---------------- gather + bias ----------------
__global__ void k_gather(const int* __restrict__ inp,
                         const float* __restrict__ b_ih,
                         const float* __restrict__ b_hh) {
    int row = blockIdx.x;              // row = t*BATCH + b
    int t = row / BATCH;
    int b = row % BATCH;
    int tok = inp[b * SEQ + t];
    const float4* src = (const float4*)&g_WihT[tok * HID];
    const float4* bi4 = (const float4*)b_ih;
    const float4* bh4 = (const float4*)b_hh;
    float4* dst = (float4*)&g_xproj[row * HID];
    int i = threadIdx.x;               // 128 threads
    float4 v = src[i];
    float4 bi = bi4[i], bh = bh4[i];
    v.x += bi.x + bh.x;  v.y += bi.y + bh.y;
    v.z += bi.z + bh.z;  v.w += bi.w + bh.w;
    dst[i] = v;
}

__global__ void k_reset() {
    if (threadIdx.x < 8) g_cnt[threadIdx.x] = 0;
}

// ---------------- recurrence v3: warp K-split + f32x2 packed FMA ----------------
// 128 CTAs = 8 batch-groups x 16 j-slices(32). 4 warps, warp w owns k in [w*128,(w+1)*128).
// smem: Ws[512][32] 64KB + hp[4][512] float2 16KB + part[16][32] u64 4KB = 84KB
extern "C" __global__ void __launch_bounds__(128, 1)
k_rnn(const float* __restrict__ Whh, const float* __restrict__ h0g) {
    extern __shared__ float sm[];
    float*  Ws   = sm;                          // [k][j] 512*32
    float2* hp   = (float2*)(sm + 512 * 32);    // [pair][k] 4*512
    u64*    part = (u64*)(hp + 4 * 512);        // [warp*4+pair][jl]

    int bx = blockIdx.x;
    int bg = bx & 7;
    int jg = bx >> 3;
    int B0 = bg * 8;
    int J0 = jg * 32;
    int tid = threadIdx.x;
    int w = tid >> 5, jl = tid & 31;
    int kbase = w * 128;

    for (int j = 0; j < 32; j++) {
        const float* wr = Whh + (J0 + j) * HID;
        for (int k = tid; k < HID; k += 128)
            Ws[k * 32 + j] = wr[k];
    }
    __syncthreads();

    unsigned target = 0;
    for (int t = 0; t < SEQ; t++) {
        // ---- stage h_{t-1} pair-interleaved into smem ----
        if (t == 0) {
            for (int idx = tid; idx < 2048; idx += 128) {
                int p = idx >> 9, k = idx & 511;
                hp[p * 512 + k] = make_float2(h0g[(B0 + 2 * p) * HID + k],
                                              h0g[(B0 + 2 * p + 1) * HID + k]);
            }
        } else {
            const float4* src = (const float4*)&g_hseq[((size_t)(t - 1) * 8 + bg) * 2048];
            float4* dst = (float4*)hp;
            #pragma unroll
            for (int i = 0; i < 8; i++)
                dst[tid + i * 128] = src[tid + i * 128];
        }
        __syncthreads();

        // ---- packed partial dot products over this warp's k-range ----
        u64 accA[4] = {0, 0, 0, 0}, accB[4] = {0, 0, 0, 0};
        const float* wptr = Ws + jl + kbase * 32;
        const ulonglong2* h2 = (const ulonglong2*)(hp + kbase);   // [k/2] within pair row
        #pragma unroll 4
        for (int i = 0; i < 64; i++) {
            float w0 = wptr[0], w1 = wptr[32];
            u64 w00 = pack2(w0, w0), w11 = pack2(w1, w1);
            #pragma unroll
            for (int p = 0; p < 4; p++) {
                ulonglong2 hv = h2[p * 256];     // (pairs at k, k+1), broadcast
                fma2(accA[p], hv.x, w00);
                fma2(accB[p], hv.y, w11);
            }
            wptr += 64;
            h2 += 1;
        }
        #pragma unroll
        for (int p = 0; p < 4; p++)
            part[(w * 4 + p) * 32 + jl] = add2(accA[p], accB[p]);
        __syncthreads();

        // ---- reduce across 4 warps, tanh, store ----
        {
            int p = tid >> 5, j2 = tid & 31;
            u64 s0 = add2(part[(0 + p) * 32 + j2], part[(4 + p) * 32 + j2]);
            u64 s1 = add2(part[(8 + p) * 32 + j2], part[(12 + p) * 32 + j2]);
            float2 s = unpack2(add2(s0, s1));
            int b0g = B0 + 2 * p;
            size_t xb = ((size_t)t * BATCH + b0g) * HID + J0 + j2;
            float r0 = tanhf(s.x + g_xproj[xb]);
            float r1 = tanhf(s.y + g_xproj[xb + HID]);
            g_hseq[((size_t)(t * 8 + bg) * 4 + p) * 512 + (J0 + j2)] = make_float2(r0, r1);
            g_A16[xb]       = __float2half_rn(r0);
            g_A16[xb + HID] = __float2half_rn(r1);
        }
        __syncthreads();

        // ---- group barrier (16 CTAs) ----
        if (t < SEQ - 1) {
            target += 16;
            if (tid == 0) {
                asm volatile("fence.acq_rel.gpu;" ::: "memory");
                asm volatile("red.relaxed.gpu.global.add.u32 [%0], %1;"
                             :: "l"(&g_cnt[bg]), "r"(1u) : "memory");
                unsigned v;
                do {
                    asm volatile("ld.acquire.gpu.global.u32 %0, [%1];"
                                 : "=r"(v) : "l"(&g_cnt[bg]));
                } while (v < target);
            }
            __syncthreads();
        }
    }
}

// ---------------- fp16 convert of W_fc ----------------
__global__ void k_convB(const float* __restrict__ Wfc) {
    size_t i = (size_t)blockIdx.x * 256 + threadIdx.x;   // float4 index
    float4 v = ((const float4*)Wfc)[i];
    __half2* hi = (__half2*)g_B16;
    hi[2 * i]     = __half2(__float2half_rn(v.x), __float2half_rn(v.y));
    hi[2 * i + 1] = __half2(__float2half_rn(v.z), __float2half_rn(v.w));
}

// ---------------- FC GEMM via mma.sync: C = A16 * B16^T (single pass) ----------------
// CTA tile 128x128, 8 warps (2m x 4n), warp tile 64x32, k-tile 32, double buffered,
// 2 CTAs/SM, ldmatrix fragment loads.
#define PITCH   40                     // halves per smem row (80 B, conflict-free)
#define TILEB   (128 * PITCH * 2)      // 10240 B per tile
#define STAGEB  (2 * TILEB)            // A, B

__global__ void __launch_bounds__(256, 2)
k_fcmma(const float* __restrict__ bfc, float* __restrict__ out) {
    extern __shared__ char dsm[];
    float* s_bias = (float*)dsm;                     // 128 floats
    uint32_t sbase = smem_u32(dsm) + 1024;           // tiles base

    int tid = threadIdx.x;
    int l = tid & 31, wid = tid >> 5;
    int m0 = blockIdx.x * 128;
    int v0 = blockIdx.y * 128;
    int mw = (wid >> 2) * 64;          // warp m offset: 0 / 64
    int nw = (wid & 3) * 32;           // warp n offset: 0/32/64/96

    if (tid < 128) s_bias[tid] = bfc[v0 + tid];

    const __half* gsrc[2] = { g_A16 + (size_t)m0 * HID, g_B16 + (size_t)v0 * HID };

    auto load_stage = [&](int s, int kt) {
        #pragma unroll
        for (int i = 0; i < 4; i++) {
            int id = tid + i * 256;          // 0..1023
            int tle = id >> 9;               // tile 0..1
            int c = id & 511;
            int r = c >> 2;                  // row 0..127
            int ch = c & 3;                  // 16B chunk 0..3
            uint32_t dst = sbase + s * STAGEB + tle * TILEB + r * 80 + ch * 16;
            cp16(dst, gsrc[tle] + (size_t)r * HID + kt * 32 + ch * 8);
        }
    };

    float acc[4][4][4];
    #pragma unroll
    for (int i = 0; i < 4; i++)
        #pragma unroll
        for (int j = 0; j < 4; j++)
            #pragma unroll
            for (int k = 0; k < 4; k++) acc[i][j][k] = 0.f;

    // ldmatrix lane addressing
    int mat = l >> 3, r8 = l & 7;
    uint32_t a_lane = (uint32_t)((mw + (mat & 1) * 8 + r8) * 80 + (mat >> 1) * 16);
    uint32_t b_lane = (uint32_t)((nw + (mat >> 1) * 8 + r8) * 80 + (mat & 1) * 16) + TILEB;

    load_stage(0, 0);
    CP_COMMIT();

    for (int kt = 0; kt < 16; kt++) {
        int buf = kt & 1;
        if (kt < 15) { load_stage(buf ^ 1, kt + 1); CP_COMMIT(); CP_WAIT(1); }
        else         { CP_WAIT(0); }
        __syncthreads();

        uint32_t sb = sbase + buf * STAGEB;
        #pragma unroll
        for (int ks = 0; ks < 2; ks++) {
            uint32_t ko = ks * 32;           // 16 halves = 32 B
            uint32_t bf[4][2];
            ldm_x4(bf[0][0], bf[0][1], bf[1][0], bf[1][1], sb + b_lane + ko);
            ldm_x4(bf[2][0], bf[2][1], bf[3][0], bf[3][1], sb + b_lane + 16 * 80 + ko);
            uint32_t af[4][4];
            #pragma unroll
            for (int fm = 0; fm < 4; fm++)
                ldm_x4(af[fm][0], af[fm][1], af[fm][2], af[fm][3],
                       sb + a_lane + fm * (16 * 80) + ko);
            #pragma unroll
            for (int fm = 0; fm < 4; fm++)
                #pragma unroll
                for (int fn = 0; fn < 4; fn++)
                    mma16816(acc[fm][fn], af[fm][0], af[fm][1], af[fm][2], af[fm][3],
                             bf[fn][0], bf[fn][1]);
        }
        __syncthreads();
    }

    // epilogue: m = t*BATCH + b -> out[b*SEQ*VOCAB + t*VOCAB + v] + bias
    #pragma unroll
    for (int fm = 0; fm < 4; fm++) {
        #pragma unroll
        for (int fn = 0; fn < 4; fn++) {
            int vloc = nw + fn * 8 + (l & 3) * 2;
            float bv0 = s_bias[vloc];
            float bv1 = s_bias[vloc + 1];
            int m = m0 + mw + fm * 16 + (l >> 2);
            int b = m & (BATCH - 1);
            int t = m >> 6;
            float2* p = (float2*)(out + (size_t)b * SEQ * VOCAB + (size_t)t * VOCAB + v0 + vloc);
            *p = make_float2(acc[fm][fn][0] + bv0, acc[fm][fn][1] + bv1);
            int m2 = m + 8;
            b = m2 & (BATCH - 1);
            t = m2 >> 6;
            p = (float2*)(out + (size_t)b * SEQ * VOCAB + (size_t)t * VOCAB + v0 + vloc);
            *p = make_float2(acc[fm][fn][2] + bv0, acc[fm][fn][3] + bv1);
        }
    }
}

// ---------------- copy h_last from g_hseq[t=511] ----------------
__global__ void k_hid(float* __restrict__ out) {
    int i = blockIdx.x * 256 + threadIdx.x;   // i = b*HID + h
    int b = i >> 9, h = i & 511;
    int bg = b >> 3, p = (b & 7) >> 1, e = b & 1;
    float2 v = g_hseq[((size_t)(511 * 8 + bg) * 4 + p) * 512 + h];
    out[i] = e ? v.y : v.x;
}

// ---------------- launcher ----------------
extern "C" void kernel_launch(void* const* d_in, const int* in_sizes, int n_in,
                              void* d_out, int out_size) {
    const int*   inp = (const int*)d_in[0];
    const float* hid = (const float*)d_in[1];
    const float* Wih = (const float*)d_in[2];
    const float* Whh = (const float*)d_in[3];
    const float* bih = (const float*)d_in[4];
    const float* bhh = (const float*)d_in[5];
    const float* Wfc = (const float*)d_in[6];
    const float* bfc = (const float*)d_in[7];
    float* out = (float*)d_out;

    cudaFuncSetAttribute(k_rnn,   cudaFuncAttributeMaxDynamicSharedMemorySize, 86016);
    cudaFuncSetAttribute(k_fcmma, cudaFuncAttributeMaxDynamicSharedMemorySize, 1024 + 2 * STAGEB);

    k_transpose<<<dim3(VOCAB / 32, HID / 32), dim3(32, 8)>>>(Wih);
    k_gather<<<SEQ * BATCH, 128>>>(inp, bih, bhh);
    k_reset<<<1, 32>>>();
    k_convB<<<(VOCAB * HID / 4) / 256, 256>>>(Wfc);
    k_rnn<<<128, 128, 86016>>>(Whh, hid);
    k_fcmma<<<dim3(MROWS / 128, VOCAB / 128), 256, 1024 + 2 * STAGEB>>>(bfc, out);

    long long logits_elems = (long long)BATCH * SEQ * VOCAB;
    if ((long long)out_size >= logits_elems + (long long)BATCH * HID) {
        k_hid<<<BATCH * HID / 256, 256>>>(out + logits_elems);
    }
}